// round 4
// baseline (speedup 1.0000x reference)
#include <cuda_runtime.h>
#include <cstdint>

// Problem constants
// B=16, T=1024, C=768, H=12, D=64, 3C=2304, M = B*T = 16384

#define DINL __device__ __forceinline__

// ---------------- scratch (device globals; no allocation allowed) ----------
__device__ float g_q [16*12*1024*64];   // [B][H][T][D]
__device__ float g_k [16*12*1024*64];
__device__ float g_v [16*12*1024*64];
__device__ float g_ao[16*1024*768];     // attention output, [B*T][C]

// ---------------- helpers ---------------------------------------------------
DINL float tf32r(float x) {
    unsigned u;
    asm("cvt.rna.tf32.f32 %0, %1;" : "=r"(u) : "f"(x));
    return __uint_as_float(u);
}

DINL void mma8(float* d, const float* a, const float* b) {
    asm volatile(
        "mma.sync.aligned.m16n8k8.row.col.f32.tf32.tf32.f32 "
        "{%0,%1,%2,%3}, {%4,%5,%6,%7}, {%8,%9}, {%0,%1,%2,%3};\n"
        : "+f"(d[0]), "+f"(d[1]), "+f"(d[2]), "+f"(d[3])
        : "r"(__float_as_uint(a[0])), "r"(__float_as_uint(a[1])),
          "r"(__float_as_uint(a[2])), "r"(__float_as_uint(a[3])),
          "r"(__float_as_uint(b[0])), "r"(__float_as_uint(b[1])));
}

// ------- 128x128x16 TF32 GEMM, smem double buffered, 1 barrier / k-iter -----
// C[M,N] = A[M,768] @ W[768,N] + bias[N]
// QKV=true : scatter into g_q/g_k/g_v as [B][H][T][D]
// QKV=false: A is g_ao, result -> out[M,768]
template<int N, bool QKV>
__global__ __launch_bounds__(256)
void gemm_kernel(const float* __restrict__ Ain, const float* __restrict__ W,
                 const float* __restrict__ bias, float* __restrict__ out)
{
    const float* A = QKV ? Ain : (const float*)g_ao;

    __shared__ float As[2][128][20];   // stride 20: A-frag pattern conflict-free
    __shared__ float Bs[2][16][136];   // stride 136: B-frag pattern conflict-free

    const int tid   = threadIdx.x;
    const int mBase = blockIdx.y * 128;
    const int nBase = blockIdx.x * 128;
    const int warp  = tid >> 5, lane = tid & 31;
    const int wm = warp >> 2, wn = warp & 3;      // 2 x 4 warp grid (64x32 tiles)
    const int g  = lane >> 2, t = lane & 3;

    // per-thread load coordinates (2 float4 each for A and B)
    int rA[2], cA[2], rB[2], cB[2];
#pragma unroll
    for (int i = 0; i < 2; i++) {
        int fi = tid + 256 * i;
        rA[i] = fi >> 2;  cA[i] = (fi & 3) << 2;
        rB[i] = fi >> 5;  cB[i] = (fi & 31) << 2;
    }

    float acc[4][4][4];
#pragma unroll
    for (int i = 0; i < 4; i++)
#pragma unroll
        for (int j = 0; j < 4; j++)
#pragma unroll
            for (int r = 0; r < 4; r++) acc[i][j][r] = 0.f;

    // prologue: tile 0 -> regs -> smem buf 0
    float4 pa[2], pb[2];
#pragma unroll
    for (int i = 0; i < 2; i++) {
        pa[i] = *(const float4*)&A[(size_t)(mBase + rA[i]) * 768 + cA[i]];
        pb[i] = *(const float4*)&W[(size_t)rB[i] * N + nBase + cB[i]];
    }
#pragma unroll
    for (int i = 0; i < 2; i++) {
        As[0][rA[i]][cA[i] + 0] = tf32r(pa[i].x); As[0][rA[i]][cA[i] + 1] = tf32r(pa[i].y);
        As[0][rA[i]][cA[i] + 2] = tf32r(pa[i].z); As[0][rA[i]][cA[i] + 3] = tf32r(pa[i].w);
        Bs[0][rB[i]][cB[i] + 0] = tf32r(pb[i].x); Bs[0][rB[i]][cB[i] + 1] = tf32r(pb[i].y);
        Bs[0][rB[i]][cB[i] + 2] = tf32r(pb[i].z); Bs[0][rB[i]][cB[i] + 3] = tf32r(pb[i].w);
    }
    __syncthreads();

    int buf = 0;
    for (int kt = 0; kt < 768; kt += 16) {
        const int kn = kt + 16;
        const bool more = (kn < 768);
        // issue next tile's global loads; latency hides under this tile's mmas
        if (more) {
#pragma unroll
            for (int i = 0; i < 2; i++) {
                pa[i] = *(const float4*)&A[(size_t)(mBase + rA[i]) * 768 + kn + cA[i]];
                pb[i] = *(const float4*)&W[(size_t)(kn + rB[i]) * N + nBase + cB[i]];
            }
        }

        // compute from current buffer
#pragma unroll
        for (int ks = 0; ks < 2; ks++) {
            float a[4][4], bf[4][2];
#pragma unroll
            for (int mi = 0; mi < 4; mi++) {
                int r0 = wm * 64 + mi * 16;
                a[mi][0] = As[buf][r0 + g    ][ks * 8 + t];
                a[mi][1] = As[buf][r0 + g + 8][ks * 8 + t];
                a[mi][2] = As[buf][r0 + g    ][ks * 8 + t + 4];
                a[mi][3] = As[buf][r0 + g + 8][ks * 8 + t + 4];
            }
#pragma unroll
            for (int ni = 0; ni < 4; ni++) {
                int c0 = wn * 32 + ni * 8;
                bf[ni][0] = Bs[buf][ks * 8 + t    ][c0 + g];
                bf[ni][1] = Bs[buf][ks * 8 + t + 4][c0 + g];
            }
#pragma unroll
            for (int mi = 0; mi < 4; mi++)
#pragma unroll
                for (int ni = 0; ni < 4; ni++)
                    mma8(acc[mi][ni], a[mi], bf[ni]);
        }

        // store next tile to the other buffer (disjoint from readers of `buf`)
        if (more) {
            const int nb = buf ^ 1;
#pragma unroll
            for (int i = 0; i < 2; i++) {
                As[nb][rA[i]][cA[i] + 0] = tf32r(pa[i].x); As[nb][rA[i]][cA[i] + 1] = tf32r(pa[i].y);
                As[nb][rA[i]][cA[i] + 2] = tf32r(pa[i].z); As[nb][rA[i]][cA[i] + 3] = tf32r(pa[i].w);
                Bs[nb][rB[i]][cB[i] + 0] = tf32r(pb[i].x); Bs[nb][rB[i]][cB[i] + 1] = tf32r(pb[i].y);
                Bs[nb][rB[i]][cB[i] + 2] = tf32r(pb[i].z); Bs[nb][rB[i]][cB[i] + 3] = tf32r(pb[i].w);
            }
            __syncthreads();
            buf = nb;
        }
    }

    // epilogue
#pragma unroll
    for (int mi = 0; mi < 4; mi++) {
#pragma unroll
        for (int ni = 0; ni < 4; ni++) {
#pragma unroll
            for (int h2 = 0; h2 < 2; h2++) {
                int row = mBase + wm * 64 + mi * 16 + g + h2 * 8;
                int col = nBase + wn * 32 + ni * 8 + 2 * t;
                float v0 = acc[mi][ni][h2 * 2 + 0] + bias[col];
                float v1 = acc[mi][ni][h2 * 2 + 1] + bias[col + 1];
                if (QKV) {
                    int which = col / 768;
                    int rem   = col - which * 768;
                    int hh = rem >> 6, dd = rem & 63;
                    int bb = row >> 10, ttk = row & 1023;
                    float* dst = (which == 0) ? g_q : (which == 1) ? g_k : g_v;
                    size_t idx = ((size_t)((bb * 12 + hh) * 1024 + ttk)) * 64 + dd;
                    *(float2*)&dst[idx] = make_float2(v0, v1);
                } else {
                    *(float2*)&out[(size_t)row * 768 + col] = make_float2(v0, v1);
                }
            }
        }
    }
}

// ---------------- flash attention (128 q x 64 k tiles, TF32 mma) ------------
// grid: (T/128=8, B*H=192), block 256 threads = 8 warps x 16 query rows.
// P never touches smem: D-frag -> A-frag conversion via quad shuffles.
struct AttnSmem {
    float Ks[64][68];   // K tile (A/B-frag pad)
    float Vs[64][72];   // V tile (B-frag pad)
    float km[64];       // key mask (1.0 = valid)
};

__global__ __launch_bounds__(256)
void attn_kernel(const int* __restrict__ mask)
{
    __shared__ AttnSmem sm;

    const int tid  = threadIdx.x, lane = tid & 31, warp = tid >> 5;
    const int g = lane >> 2, t = lane & 3;
    const int bh    = blockIdx.y;
    const int b     = bh / 12;
    const int h     = bh - b * 12;
    const int qbase = blockIdx.x * 128;
    const int qr0   = warp * 16;                 // warp's q-row offset in tile
    const size_t base = (size_t)bh * 1024 * 64;

    const float SC = 0.18033688f;  // (1/sqrt(64)) * log2(e): softmax in exp2 domain

    // shuffle source lanes for D->A fragment conversion (quad-scope)
    const int qb  = lane & 28;
    const int sl0 = qb | (t >> 1);           // col t
    const int sl1 = qb | ((t >> 1) + 2);     // col t+4
    const bool odd = (t & 1);

    // ---- load Q fragments directly from gmem (one-time) ----
    float qa[8][4];
    {
        const float* qp = &g_q[base + (size_t)(qbase + qr0) * 64];
#pragma unroll
        for (int ks = 0; ks < 8; ks++) {
            qa[ks][0] = tf32r(qp[(g    ) * 64 + ks * 8 + t    ]);
            qa[ks][1] = tf32r(qp[(g + 8) * 64 + ks * 8 + t    ]);
            qa[ks][2] = tf32r(qp[(g    ) * 64 + ks * 8 + t + 4]);
            qa[ks][3] = tf32r(qp[(g + 8) * 64 + ks * 8 + t + 4]);
        }
    }

    float o[8][4];
#pragma unroll
    for (int ni = 0; ni < 8; ni++)
#pragma unroll
        for (int r = 0; r < 4; r++) o[ni][r] = 0.f;
    float mrow[2] = {-1e30f, -1e30f};
    float lrow[2] = {0.f, 0.f};

    const int nkt = 2 * blockIdx.x + 2;          // k-tiles covering rows <= qbase+127
    for (int kt = 0; kt < nkt; kt++) {
        const int kbase = kt * 64;
        // ---- load K, V tiles + key mask (all warps) ----
#pragma unroll
        for (int i = 0; i < 4; i++) {
            int fi = tid + 256 * i;              // 0..1023 float4s
            int row = fi >> 4, c4 = (fi & 15) << 2;
            float4 kv = *(const float4*)&g_k[base + (size_t)(kbase + row) * 64 + c4];
            sm.Ks[row][c4 + 0] = tf32r(kv.x); sm.Ks[row][c4 + 1] = tf32r(kv.y);
            sm.Ks[row][c4 + 2] = tf32r(kv.z); sm.Ks[row][c4 + 3] = tf32r(kv.w);
            float4 vv = *(const float4*)&g_v[base + (size_t)(kbase + row) * 64 + c4];
            sm.Vs[row][c4 + 0] = tf32r(vv.x); sm.Vs[row][c4 + 1] = tf32r(vv.y);
            sm.Vs[row][c4 + 2] = tf32r(vv.z); sm.Vs[row][c4 + 3] = tf32r(vv.w);
        }
        if (tid < 64)
            sm.km[tid] = (mask[b * 1024 + kbase + tid] != 0) ? 1.f : 0.f;
        __syncthreads();

        // warp-level skip: tile entirely above this warp's causal boundary.
        // Exact: those entries are -1e9 -> exp ~ 0 against an O(1) running max.
        const bool active = (kbase <= qbase + qr0 + 15);
        if (active) {
            // ---- S = Q @ K^T ----
            float s[8][4];
#pragma unroll
            for (int ni = 0; ni < 8; ni++)
#pragma unroll
                for (int r = 0; r < 4; r++) s[ni][r] = 0.f;
#pragma unroll
            for (int ks = 0; ks < 8; ks++) {
#pragma unroll
                for (int ni = 0; ni < 8; ni++) {
                    float bf[2];
                    bf[0] = sm.Ks[ni * 8 + g][ks * 8 + t];
                    bf[1] = sm.Ks[ni * 8 + g][ks * 8 + t + 4];
                    mma8(s[ni], qa[ks], bf);
                }
            }

            // ---- scale + key mask + causal mask (global indices) ----
#pragma unroll
            for (int ni = 0; ni < 8; ni++) {
#pragma unroll
                for (int r = 0; r < 4; r++) {
                    int gcol = kbase + ni * 8 + 2 * t + (r & 1);
                    int grow = qbase + qr0 + g + ((r & 2) << 2);
                    float sv = s[ni][r] * SC;
                    bool ok  = (sm.km[ni * 8 + 2 * t + (r & 1)] != 0.f) && (gcol <= grow);
                    s[ni][r] = ok ? sv : -1e9f;
                }
            }

            // ---- online softmax (exp2 domain) ----
#pragma unroll
            for (int rh = 0; rh < 2; rh++) {
                float tmax = -1e30f;
#pragma unroll
                for (int ni = 0; ni < 8; ni++) {
                    tmax = fmaxf(tmax, s[ni][2 * rh]);
                    tmax = fmaxf(tmax, s[ni][2 * rh + 1]);
                }
                tmax = fmaxf(tmax, __shfl_xor_sync(0xffffffffu, tmax, 1));
                tmax = fmaxf(tmax, __shfl_xor_sync(0xffffffffu, tmax, 2));
                float mnew = fmaxf(mrow[rh], tmax);
                float corr = exp2f(mrow[rh] - mnew);
                float tsum = 0.f;
#pragma unroll
                for (int ni = 0; ni < 8; ni++) {
                    float p0 = exp2f(s[ni][2 * rh]     - mnew);
                    float p1 = exp2f(s[ni][2 * rh + 1] - mnew);
                    s[ni][2 * rh] = p0; s[ni][2 * rh + 1] = p1;
                    tsum += p0 + p1;
                }
                tsum += __shfl_xor_sync(0xffffffffu, tsum, 1);
                tsum += __shfl_xor_sync(0xffffffffu, tsum, 2);
                lrow[rh] = lrow[rh] * corr + tsum;
                mrow[rh] = mnew;
#pragma unroll
                for (int ni = 0; ni < 8; ni++) {
                    o[ni][2 * rh]     *= corr;
                    o[ni][2 * rh + 1] *= corr;
                }
            }

            // ---- O += P @ V : per-ks A-frag of P built via quad shuffles ----
#pragma unroll
            for (int ks = 0; ks < 8; ks++) {
                // P block cols [8ks, 8ks+8): D-layout s[ks][*] -> A-layout
                float e0 = __shfl_sync(0xffffffffu, s[ks][0], sl0);
                float o0 = __shfl_sync(0xffffffffu, s[ks][1], sl0);
                float e1 = __shfl_sync(0xffffffffu, s[ks][2], sl0);
                float o1 = __shfl_sync(0xffffffffu, s[ks][3], sl0);
                float e2 = __shfl_sync(0xffffffffu, s[ks][0], sl1);
                float o2 = __shfl_sync(0xffffffffu, s[ks][1], sl1);
                float e3 = __shfl_sync(0xffffffffu, s[ks][2], sl1);
                float o3 = __shfl_sync(0xffffffffu, s[ks][3], sl1);
                float a[4];
                a[0] = tf32r(odd ? o0 : e0);   // (g,    t  )
                a[1] = tf32r(odd ? o1 : e1);   // (g+8,  t  )
                a[2] = tf32r(odd ? o2 : e2);   // (g,    t+4)
                a[3] = tf32r(odd ? o3 : e3);   // (g+8,  t+4)
#pragma unroll
                for (int ni = 0; ni < 8; ni++) {
                    float bf[2];
                    bf[0] = sm.Vs[ks * 8 + t    ][ni * 8 + g];
                    bf[1] = sm.Vs[ks * 8 + t + 4][ni * 8 + g];
                    mma8(o[ni], a, bf);
                }
            }
        }
        __syncthreads();   // all reads of Ks/Vs done before next tile load
    }

    // ---- finalize: 1/l, query mask, write [B*T][C] ----
#pragma unroll
    for (int rh = 0; rh < 2; rh++) {
        int qrow = qbase + qr0 + g + rh * 8;
        float inv = 1.f / lrow[rh];
        float qm  = (mask[b * 1024 + qrow] != 0) ? inv : 0.f;
        size_t rowbase = ((size_t)(b * 1024 + qrow)) * 768 + h * 64;
#pragma unroll
        for (int ni = 0; ni < 8; ni++) {
            float2 v2 = make_float2(o[ni][2 * rh] * qm, o[ni][2 * rh + 1] * qm);
            *(float2*)&g_ao[rowbase + ni * 8 + 2 * t] = v2;
        }
    }
}

// ---------------- launch -----------------------------------------------------
extern "C" void kernel_launch(void* const* d_in, const int* in_sizes, int n_in,
                              void* d_out, int out_size)
{
    (void)in_sizes; (void)n_in; (void)out_size;
    const float* x      = (const float*)d_in[0];
    const int*   mask   = (const int*)  d_in[1];
    const float* W_attn = (const float*)d_in[2];
    const float* b_attn = (const float*)d_in[3];
    const float* W_proj = (const float*)d_in[4];
    const float* b_proj = (const float*)d_in[5];
    float* out = (float*)d_out;

    // 1) QKV projection -> g_q/g_k/g_v ([B][H][T][D])
    gemm_kernel<2304, true><<<dim3(18, 128), 256>>>(x, W_attn, b_attn, nullptr);
    // 2) causal masked flash attention -> g_ao ([B*T][C])
    attn_kernel<<<dim3(8, 192), 256>>>(mask);
    // 3) output projection -> d_out
    gemm_kernel<768, false><<<dim3(6, 128), 256>>>(nullptr, W_proj, b_proj, out);
}

// round 6
// speedup vs baseline: 1.1407x; 1.1407x over previous
#include <cuda_runtime.h>
#include <cstdint>

// Problem constants: B=16, T=1024, C=768, H=12, D=64, 3C=2304, M=B*T=16384

#define DINL __device__ __forceinline__

// ---------------- scratch (device globals; no allocation allowed) ----------
__device__ float g_q [16*12*1024*64];   // [B][H][T][D]  (tf32-rounded)
__device__ float g_k [16*12*1024*64];
__device__ float g_v [16*12*1024*64];
__device__ float g_ao[16*1024*768];     // attention output, [B*T][C] (tf32-rounded)
__device__ float g_xr[16384*768];       // tf32-rounded x
__device__ float g_wa[768*2304];        // tf32-rounded W_attn
__device__ float g_wp[768*768];         // tf32-rounded W_proj

// ---------------- helpers ---------------------------------------------------
DINL float tf32r(float x) {
    unsigned u;
    asm("cvt.rna.tf32.f32 %0, %1;" : "=r"(u) : "f"(x));
    return __uint_as_float(u);
}

DINL uint32_t smem_u32(const void* p) {
    uint32_t a;
    asm("{ .reg .u64 t; cvta.to.shared.u64 t, %1; cvt.u32.u64 %0, t; }"
        : "=r"(a) : "l"(p));
    return a;
}

DINL void mma8(float* d, const float* a, const float* b) {
    asm volatile(
        "mma.sync.aligned.m16n8k8.row.col.f32.tf32.tf32.f32 "
        "{%0,%1,%2,%3}, {%4,%5,%6,%7}, {%8,%9}, {%0,%1,%2,%3};\n"
        : "+f"(d[0]), "+f"(d[1]), "+f"(d[2]), "+f"(d[3])
        : "r"(__float_as_uint(a[0])), "r"(__float_as_uint(a[1])),
          "r"(__float_as_uint(a[2])), "r"(__float_as_uint(a[3])),
          "r"(__float_as_uint(b[0])), "r"(__float_as_uint(b[1])));
}

DINL void cp16(uint32_t smem_dst, const void* gsrc) {
    asm volatile("cp.async.cg.shared.global [%0], [%1], 16;\n"
                 :: "r"(smem_dst), "l"(gsrc) : "memory");
}
#define CP_COMMIT() asm volatile("cp.async.commit_group;\n" ::: "memory")
#define CP_WAIT(n)  asm volatile("cp.async.wait_group %0;\n" :: "n"(n) : "memory")

// ---------------- elementwise tf32 rounding prepass -------------------------
__global__ __launch_bounds__(256)
void round_kernel(const float* __restrict__ in, float* __restrict__ out, int n4)
{
    int i = blockIdx.x * blockDim.x + threadIdx.x;
    if (i < n4) {
        float4 v = ((const float4*)in)[i];
        v.x = tf32r(v.x); v.y = tf32r(v.y); v.z = tf32r(v.z); v.w = tf32r(v.w);
        ((float4*)out)[i] = v;
    }
}

// ------- 128x128x16 TF32 GEMM: cp.async 3-stage pipeline, swizzled smem -----
// C[M,N] = A[M,768] @ W[768,N] + bias[N].  A and W are pre-rounded to tf32.
// QKV=true : scatter into g_q/g_k/g_v as [B][H][T][D] (tf32-rounded)
// QKV=false: result -> out[M,768] (full fp32)
struct GSmem {
    float A[3][128 * 16];   // 8KB/stage, row=64B, chunk swizzle ^((row>>1)&3)
    float B[3][16 * 128];   // 8KB/stage, row=512B, chunk swizzle ^(2*(row&3))
};                          // 48KB total

template<int N, bool QKV>
__global__ __launch_bounds__(256)
void gemm_kernel(const float* __restrict__ A, const float* __restrict__ W,
                 const float* __restrict__ bias, float* __restrict__ out)
{
    __shared__ GSmem sm;

    const int tid   = threadIdx.x;
    const int mBase = blockIdx.y * 128;
    const int nBase = blockIdx.x * 128;
    const int warp  = tid >> 5, lane = tid & 31;
    const int wm = warp >> 2, wn = warp & 3;      // 2 x 4 warp grid (64x32 tiles)
    const int g  = lane >> 2, t = lane & 3;
    const int swA = (g >> 1) & 3;                 // A-frag row-swizzle key

    // staging coordinates (2 x 16B chunks each for A and B per thread)
    int arow[2], acq[2], asw[2], brow[2], bcc[2], bsw[2];
#pragma unroll
    for (int j = 0; j < 2; j++) {
        int q = tid + 256 * j;
        arow[j] = q >> 2;  acq[j] = q & 3;
        asw[j]  = acq[j] ^ ((arow[j] >> 1) & 3);
        brow[j] = q >> 5;  bcc[j] = q & 31;
        bsw[j]  = bcc[j] ^ (2 * (brow[j] & 3));
    }
    const uint32_t aBase = smem_u32(sm.A);
    const uint32_t bBase = smem_u32(sm.B);

    float acc[4][4][4];
#pragma unroll
    for (int i = 0; i < 4; i++)
#pragma unroll
        for (int j = 0; j < 4; j++)
#pragma unroll
            for (int r = 0; r < 4; r++) acc[i][j][r] = 0.f;

    // stage issuer
    auto stage = [&](int s, int kt) {
#pragma unroll
        for (int j = 0; j < 2; j++) {
            cp16(aBase + (uint32_t)(s * 2048 + arow[j] * 16 + asw[j] * 4) * 4,
                 &A[(size_t)(mBase + arow[j]) * 768 + kt + acq[j] * 4]);
            cp16(bBase + (uint32_t)(s * 2048 + brow[j] * 128 + bsw[j] * 4) * 4,
                 &W[(size_t)(kt + brow[j]) * N + nBase + bcc[j] * 4]);
        }
        CP_COMMIT();
    };

    stage(0, 0);
    stage(1, 16);

    int cur = 0, nx = 2;
    for (int i = 0; i < 48; i++) {
        if (i + 2 < 48) { CP_WAIT(1); } else { CP_WAIT(0); }
        __syncthreads();
        if (i + 2 < 48) stage(nx, (i + 2) * 16);

        const float* Ab = &sm.A[cur][0];
        const float* Bb = &sm.B[cur][0];
#pragma unroll
        for (int ks = 0; ks < 2; ks++) {
            float a[4][4], bf[4][2];
#pragma unroll
            for (int mi = 0; mi < 4; mi++) {
                int r0  = wm * 64 + mi * 16 + g;
                int c0x = ((2 * ks)     ^ swA) * 4 + t;
                int c1x = ((2 * ks + 1) ^ swA) * 4 + t;
                a[mi][0] = Ab[(r0    ) * 16 + c0x];
                a[mi][1] = Ab[(r0 + 8) * 16 + c0x];
                a[mi][2] = Ab[(r0    ) * 16 + c1x];
                a[mi][3] = Ab[(r0 + 8) * 16 + c1x];
            }
#pragma unroll
            for (int ni = 0; ni < 4; ni++) {
                int cidx = ((8 * wn + 2 * ni + (g >> 2)) ^ (2 * t)) * 4 + (g & 3);
                bf[ni][0] = Bb[(ks * 8 + t    ) * 128 + cidx];
                bf[ni][1] = Bb[(ks * 8 + t + 4) * 128 + cidx];
            }
#pragma unroll
            for (int mi = 0; mi < 4; mi++)
#pragma unroll
                for (int ni = 0; ni < 4; ni++)
                    mma8(acc[mi][ni], a[mi], bf[ni]);
        }
        cur = (cur == 2) ? 0 : cur + 1;
        nx  = (nx  == 2) ? 0 : nx  + 1;
    }

    // epilogue
#pragma unroll
    for (int mi = 0; mi < 4; mi++) {
#pragma unroll
        for (int ni = 0; ni < 4; ni++) {
#pragma unroll
            for (int h2 = 0; h2 < 2; h2++) {
                int row = mBase + wm * 64 + mi * 16 + g + h2 * 8;
                int col = nBase + wn * 32 + ni * 8 + 2 * t;
                float v0 = acc[mi][ni][h2 * 2 + 0] + bias[col];
                float v1 = acc[mi][ni][h2 * 2 + 1] + bias[col + 1];
                if (QKV) {
                    int which = col / 768;
                    int rem   = col - which * 768;
                    int hh = rem >> 6, dd = rem & 63;
                    int bb = row >> 10, ttk = row & 1023;
                    float* dst = (which == 0) ? g_q : (which == 1) ? g_k : g_v;
                    size_t idx = ((size_t)((bb * 12 + hh) * 1024 + ttk)) * 64 + dd;
                    *(float2*)&dst[idx] = make_float2(tf32r(v0), tf32r(v1));
                } else {
                    *(float2*)&out[(size_t)row * 768 + col] = make_float2(v0, v1);
                }
            }
        }
    }
}

// ---------------- flash attention (128 q x 64 k tiles, TF32 mma) ------------
// grid: (T/128=8, B*H=192), block 256 threads = 8 warps x 16 query rows.
// Q/K/V are pre-rounded tf32 -> no conversion on load.
struct AttnSmem {
    float Ks[64][68];   // K tile (A/B-frag pad)
    float Vs[64][72];   // V tile (B-frag pad)
    float km[64];       // key mask (1.0 = valid)
};

__global__ __launch_bounds__(256)
void attn_kernel(const int* __restrict__ mask)
{
    __shared__ AttnSmem sm;

    const int tid  = threadIdx.x, lane = tid & 31, warp = tid >> 5;
    const int g = lane >> 2, t = lane & 3;
    const int bh    = blockIdx.y;
    const int b     = bh / 12;
    const int h     = bh - b * 12;
    const int qbase = blockIdx.x * 128;
    const int qr0   = warp * 16;
    const size_t base = (size_t)bh * 1024 * 64;

    const float SC = 0.18033688f;  // (1/sqrt(64)) * log2(e)

    const int qb  = lane & 28;
    const int sl0 = qb | (t >> 1);
    const int sl1 = qb | ((t >> 1) + 2);
    const bool odd = (t & 1);

    float qa[8][4];
    {
        const float* qp = &g_q[base + (size_t)(qbase + qr0) * 64];
#pragma unroll
        for (int ks = 0; ks < 8; ks++) {
            qa[ks][0] = qp[(g    ) * 64 + ks * 8 + t    ];
            qa[ks][1] = qp[(g + 8) * 64 + ks * 8 + t    ];
            qa[ks][2] = qp[(g    ) * 64 + ks * 8 + t + 4];
            qa[ks][3] = qp[(g + 8) * 64 + ks * 8 + t + 4];
        }
    }

    float o[8][4];
#pragma unroll
    for (int ni = 0; ni < 8; ni++)
#pragma unroll
        for (int r = 0; r < 4; r++) o[ni][r] = 0.f;
    float mrow[2] = {-1e30f, -1e30f};
    float lrow[2] = {0.f, 0.f};

    const int nkt = 2 * blockIdx.x + 2;
    for (int kt = 0; kt < nkt; kt++) {
        const int kbase = kt * 64;
#pragma unroll
        for (int i = 0; i < 4; i++) {
            int fi = tid + 256 * i;
            int row = fi >> 4, c4 = (fi & 15) << 2;
            float4 kv = *(const float4*)&g_k[base + (size_t)(kbase + row) * 64 + c4];
            sm.Ks[row][c4 + 0] = kv.x; sm.Ks[row][c4 + 1] = kv.y;
            sm.Ks[row][c4 + 2] = kv.z; sm.Ks[row][c4 + 3] = kv.w;
            float4 vv = *(const float4*)&g_v[base + (size_t)(kbase + row) * 64 + c4];
            sm.Vs[row][c4 + 0] = vv.x; sm.Vs[row][c4 + 1] = vv.y;
            sm.Vs[row][c4 + 2] = vv.z; sm.Vs[row][c4 + 3] = vv.w;
        }
        if (tid < 64)
            sm.km[tid] = (mask[b * 1024 + kbase + tid] != 0) ? 1.f : 0.f;
        __syncthreads();

        const bool active = (kbase <= qbase + qr0 + 15);
        if (active) {
            float s[8][4];
#pragma unroll
            for (int ni = 0; ni < 8; ni++)
#pragma unroll
                for (int r = 0; r < 4; r++) s[ni][r] = 0.f;
#pragma unroll
            for (int ks = 0; ks < 8; ks++) {
#pragma unroll
                for (int ni = 0; ni < 8; ni++) {
                    float bf[2];
                    bf[0] = sm.Ks[ni * 8 + g][ks * 8 + t];
                    bf[1] = sm.Ks[ni * 8 + g][ks * 8 + t + 4];
                    mma8(s[ni], qa[ks], bf);
                }
            }

#pragma unroll
            for (int ni = 0; ni < 8; ni++) {
#pragma unroll
                for (int r = 0; r < 4; r++) {
                    int gcol = kbase + ni * 8 + 2 * t + (r & 1);
                    int grow = qbase + qr0 + g + ((r & 2) << 2);
                    float sv = s[ni][r] * SC;
                    bool ok  = (sm.km[ni * 8 + 2 * t + (r & 1)] != 0.f) && (gcol <= grow);
                    s[ni][r] = ok ? sv : -1e9f;
                }
            }

#pragma unroll
            for (int rh = 0; rh < 2; rh++) {
                float tmax = -1e30f;
#pragma unroll
                for (int ni = 0; ni < 8; ni++) {
                    tmax = fmaxf(tmax, s[ni][2 * rh]);
                    tmax = fmaxf(tmax, s[ni][2 * rh + 1]);
                }
                tmax = fmaxf(tmax, __shfl_xor_sync(0xffffffffu, tmax, 1));
                tmax = fmaxf(tmax, __shfl_xor_sync(0xffffffffu, tmax, 2));
                float mnew = fmaxf(mrow[rh], tmax);
                float corr = exp2f(mrow[rh] - mnew);
                float tsum = 0.f;
#pragma unroll
                for (int ni = 0; ni < 8; ni++) {
                    float p0 = exp2f(s[ni][2 * rh]     - mnew);
                    float p1 = exp2f(s[ni][2 * rh + 1] - mnew);
                    s[ni][2 * rh] = p0; s[ni][2 * rh + 1] = p1;
                    tsum += p0 + p1;
                }
                tsum += __shfl_xor_sync(0xffffffffu, tsum, 1);
                tsum += __shfl_xor_sync(0xffffffffu, tsum, 2);
                lrow[rh] = lrow[rh] * corr + tsum;
                mrow[rh] = mnew;
#pragma unroll
                for (int ni = 0; ni < 8; ni++) {
                    o[ni][2 * rh]     *= corr;
                    o[ni][2 * rh + 1] *= corr;
                }
            }

#pragma unroll
            for (int ks = 0; ks < 8; ks++) {
                float e0 = __shfl_sync(0xffffffffu, s[ks][0], sl0);
                float o0 = __shfl_sync(0xffffffffu, s[ks][1], sl0);
                float e1 = __shfl_sync(0xffffffffu, s[ks][2], sl0);
                float o1 = __shfl_sync(0xffffffffu, s[ks][3], sl0);
                float e2 = __shfl_sync(0xffffffffu, s[ks][0], sl1);
                float o2 = __shfl_sync(0xffffffffu, s[ks][1], sl1);
                float e3 = __shfl_sync(0xffffffffu, s[ks][2], sl1);
                float o3 = __shfl_sync(0xffffffffu, s[ks][3], sl1);
                float a[4];
                a[0] = tf32r(odd ? o0 : e0);
                a[1] = tf32r(odd ? o1 : e1);
                a[2] = tf32r(odd ? o2 : e2);
                a[3] = tf32r(odd ? o3 : e3);
#pragma unroll
                for (int ni = 0; ni < 8; ni++) {
                    float bf[2];
                    bf[0] = sm.Vs[ks * 8 + t    ][ni * 8 + g];
                    bf[1] = sm.Vs[ks * 8 + t + 4][ni * 8 + g];
                    mma8(o[ni], a, bf);
                }
            }
        }
        __syncthreads();
    }

    // finalize: 1/l, query mask, tf32-round (proj GEMM operand), write
#pragma unroll
    for (int rh = 0; rh < 2; rh++) {
        int qrow = qbase + qr0 + g + rh * 8;
        float inv = 1.f / lrow[rh];
        float qm  = (mask[b * 1024 + qrow] != 0) ? inv : 0.f;
        size_t rowbase = ((size_t)(b * 1024 + qrow)) * 768 + h * 64;
#pragma unroll
        for (int ni = 0; ni < 8; ni++) {
            float2 v2 = make_float2(tf32r(o[ni][2 * rh] * qm),
                                    tf32r(o[ni][2 * rh + 1] * qm));
            *(float2*)&g_ao[rowbase + ni * 8 + 2 * t] = v2;
        }
    }
}

// ---------------- launch -----------------------------------------------------
extern "C" void kernel_launch(void* const* d_in, const int* in_sizes, int n_in,
                              void* d_out, int out_size)
{
    (void)in_sizes; (void)n_in; (void)out_size;
    const float* x      = (const float*)d_in[0];
    const int*   mask   = (const int*)  d_in[1];
    const float* W_attn = (const float*)d_in[2];
    const float* b_attn = (const float*)d_in[3];
    const float* W_proj = (const float*)d_in[4];
    const float* b_proj = (const float*)d_in[5];
    float* out = (float*)d_out;

    float* xr; cudaGetSymbolAddress((void**)&xr, g_xr);
    float* wa; cudaGetSymbolAddress((void**)&wa, g_wa);
    float* wp; cudaGetSymbolAddress((void**)&wp, g_wp);
    float* ao; cudaGetSymbolAddress((void**)&ao, g_ao);

    // 0) tf32-round GEMM operands (cp.async path can't convert in-flight)
    round_kernel<<<(16384 * 768 / 4 + 255) / 256, 256>>>(x,      xr, 16384 * 768 / 4);
    round_kernel<<<(768 * 2304 / 4 + 255) / 256, 256>>>(W_attn, wa, 768 * 2304 / 4);
    round_kernel<<<(768 * 768  / 4 + 255) / 256, 256>>>(W_proj, wp, 768 * 768 / 4);
    // 1) QKV projection -> g_q/g_k/g_v ([B][H][T][D], tf32-rounded)
    gemm_kernel<2304, true><<<dim3(18, 128), 256>>>(xr, wa, b_attn, nullptr);
    // 2) causal masked flash attention -> g_ao (tf32-rounded)
    attn_kernel<<<dim3(8, 192), 256>>>(mask);
    // 3) output projection -> d_out (full fp32)
    gemm_kernel<768, false><<<dim3(6, 128), 256>>>(ao, wp, b_proj, out);
}